// round 14
// baseline (speedup 1.0000x reference)
#include <cuda_runtime.h>

// ---------------- problem constants ----------------
#define NB 4
#define NC 512
#define NG 2048
#define CH 3
#define NP 3
#define NBAS 10
#define OC 64
#define EPSF 1e-6f
#define BNEPS 1e-5f
#define LOG2E_F 1.4426950408889634f
#define PI2F 6.283185307179586f
#define INV2PI_F 0.15915494309189535f
#define PI2_D 6.2831853071795864769
#define SQRT_2_OVER_NBAS 0.4472135954999579f

#define SPLIT 8
#define NCHUNK (NC / SPLIT)   // 64
#define TILE_G 64
#define GTILES (NG / TILE_G)  // 32

#define ELEMS (NB * NG * CH * NP)  // 73728

// fused combine/conv kernel tiling
#define FG 16
#define FBLOCKS (NB * (NG / FG))    // 512
#define FTHREADS 224
#define HALO 4
#define FGH (FG + 2 * HALO)         // 24
#define FCONV (9 * FG)              // 144

// final kernel tiling: block = 32 positions x 64 oc (8 positions per thread)
#define K5_POS 32
#define K5_BLOCKS ((NB * NG) / K5_POS)  // 256

// output offsets (flattened tuple concat: y_out, n_f, fourier, n_h1, h0_f)
#define OFF_NF  (NB * NG * OC)        // 524288
#define OFF_FP  (OFF_NF + ELEMS)      // 598016
#define OFF_NH1 (OFF_FP + ELEMS)      // 671744
#define OFF_H0  (OFF_NH1 + ELEMS)     // 745472

// ---------------- scratch (no allocs allowed) ----------------
__device__ float g_ph0[SPLIT * ELEMS];
__device__ float g_ph1[SPLIT * ELEMS];
__device__ float g_conv[ELEMS];             // conv output (pre-BN)
__device__ float g_h0s [ELEMS];             // h0 mirror (L2-hot feat source for k5)
__device__ float g_psum[9 * FBLOCKS];       // per-cp per-block partial sums
__device__ float g_psq [9 * FBLOCKS];       // per-cp per-block partial sum-squares
__device__ float g_bnA[9];                  // folded BN: v*A + B
__device__ float g_bnB[9];
__device__ float g_gwt[18 * OC];            // g_w transposed: [k][oc] (coalesced reads)

__device__ __forceinline__ float ex2f(float x) {
    float y;
    asm("ex2.approx.ftz.f32 %0, %1;" : "=f"(y) : "f"(x));
    return y;
}

// ---------------- kernel 1: RBF pairwise partial sums (lean scalar, dense) ----------------
// grid: NB * GTILES * SPLIT = 1024 blocks, block: 192 threads (6 warps).
// warp w: c = w % 3 (uniform), g = gt*64 + (w/3)*32 + lane.
// Scalar math, float2 shared loads, 12 even/odd accumulators. MUFU-bound (measured 14.8us).
__global__ __launch_bounds__(CH * TILE_G) void k1_rbf(
    const float* __restrict__ x_c, const float* __restrict__ y_c,
    const float* __restrict__ x_g, const float* __restrict__ sigma)
{
    __shared__ __align__(8) float sxp[NCHUNK * CH];  // pair-interleaved x
    __shared__ __align__(8) float syp[NCHUNK * CH];

    int unit = blockIdx.x;
    int s  = unit % SPLIT;
    int gt = (unit / SPLIT) % GTILES;
    int b  = unit / (SPLIT * GTILES);

    int lane = threadIdx.x & 31;
    int w    = threadIdx.x >> 5;       // 0..5
    int c    = w % 3;                  // uniform per warp
    int g    = gt * TILE_G + (w / 3) * 32 + lane;
    int n0   = s * NCHUNK;

    const float* xb = x_c + (b * NC + n0) * CH;
    const float* yb = y_c + (b * NC + n0) * CH;
    for (int i = threadIdx.x; i < NCHUNK * CH; i += blockDim.x) {
        int n = i / CH, cc = i % CH;
        int slot = ((n >> 1) * CH + cc) * 2 + (n & 1);
        sxp[slot] = xb[i];
        syp[slot] = yb[i];
    }
    __syncthreads();

    float xg = x_g[(b * NG + g) * CH + c];

    float s0 = expf(sigma[0]) + EPSF;
    float s1 = expf(sigma[1]) + EPSF;
    float s2 = expf(sigma[2]) + EPSF;
    float k0 = -0.5f * LOG2E_F / (s0 * s0);
    float k1 = -0.5f * LOG2E_F / (s1 * s1);
    float k2 = -0.5f * LOG2E_F / (s2 * s2);

    float h00e = 0.f, h01e = 0.f, h02e = 0.f;
    float h00o = 0.f, h01o = 0.f, h02o = 0.f;
    float h10e = 0.f, h11e = 0.f, h12e = 0.f;
    float h10o = 0.f, h11o = 0.f, h12o = 0.f;

    const float2* sx2 = (const float2*)sxp;
    const float2* sy2 = (const float2*)syp;

#pragma unroll 8
    for (int n2 = 0; n2 < NCHUNK / 2; n2++) {
        float2 xv = sx2[n2 * CH + c];   // broadcast LDS.64 (warp-uniform addr)
        float2 yv = sy2[n2 * CH + c];
        float d0 = xg - xv.x;
        float d1 = xg - xv.y;
        float t0 = d0 * d0;
        float t1 = d1 * d1;
        float wv;
        wv = ex2f(t0 * k0); h00e += wv; h10e = fmaf(wv, yv.x, h10e);
        wv = ex2f(t1 * k0); h00o += wv; h10o = fmaf(wv, yv.y, h10o);
        wv = ex2f(t0 * k1); h01e += wv; h11e = fmaf(wv, yv.x, h11e);
        wv = ex2f(t1 * k1); h01o += wv; h11o = fmaf(wv, yv.y, h11o);
        wv = ex2f(t0 * k2); h02e += wv; h12e = fmaf(wv, yv.x, h12e);
        wv = ex2f(t1 * k2); h02o += wv; h12o = fmaf(wv, yv.y, h12o);
    }

    int base = ((b * NG + g) * CH + c) * NP;
    int off  = s * ELEMS + base;
    g_ph0[off + 0] = h00e + h00o;
    g_ph0[off + 1] = h01e + h01o;
    g_ph0[off + 2] = h02e + h02o;
    g_ph1[off + 0] = h10e + h10o;
    g_ph1[off + 1] = h11e + h11o;
    g_ph1[off + 2] = h12e + h12o;
}

// fp32 Cody-Waite cos for args up to ~2e5: two single-rounding FMAs remove
// n*2pi, then hardware cos on |r| <= pi+eps. abs err ~7e-7, no FP64.
__device__ __forceinline__ float cos_red(float arg) {
    const float F2PI     = (float)PI2_D;
    const float F2PI_RES = (float)(PI2_D - (double)((float)PI2_D));
    float n = rintf(arg * INV2PI_F);
    float r = fmaf(-n, F2PI, arg);
    r = fmaf(-n, F2PI_RES, r);
    return __cosf(r);
}

// ---------------- kernel F: combine + Fourier prior + depthwise conv + BN partials ----------------
// grid: 512 blocks (b x g-tile of 16), 224 threads.
__global__ __launch_bounds__(FTHREADS) void kF_fused(
    const float* __restrict__ x_g, const float* __restrict__ sigma,
    const float* __restrict__ mu,  const float* __restrict__ eps1,
    const float* __restrict__ b_u, const float* __restrict__ rw,
    const float* __restrict__ w1, const float* __restrict__ b1,
    const float* __restrict__ w2, const float* __restrict__ b2,
    const float* __restrict__ w3, const float* __restrict__ b3,
    float* __restrict__ out)
{
    __shared__ float spos[FGH * 9];       // 216
    __shared__ float ssw[NBAS * 3];
    __shared__ float ssb[NBAS * 3];
    __shared__ float srw[NBAS];

    int tid = threadIdx.x;
    int b   = blockIdx.x / (NG / FG);
    int gt  = blockIdx.x % (NG / FG);
    int g0  = gt * FG;

    if (tid < NBAS * 3) {
        int k = tid / 3, p = tid % 3;
        float wmu  = expf(mu[p]);
        float wstd = 1.0f / (expf(sigma[p]) + EPSF);
        float e = eps1[(b * NBAS + k) * NP + p];
        float u = b_u [(b * NBAS + k) * NP + p];
        ssw[tid] = __fadd_rn(wmu, __fmul_rn(wstd, e));
        ssb[tid] = __fmul_rn(PI2F, u);
    }
    if (tid < NBAS) srw[tid] = rw[tid];
    __syncthreads();

    // Phase 1: pos = n_h1 + fourier, one element per thread
    if (tid < FGH * 9) {
        int jj = tid / 9;
        int cp = tid % 9;
        int c = cp / 3, p = cp % 3;
        int g = g0 - HALO + jj;
        float pos = 0.f;
        if (g >= 0 && g < NG) {
            int idx = ((b * NG + g) * CH + c) * NP + p;
            float h0 = 0.f, h1 = 0.f;
#pragma unroll
            for (int s = 0; s < SPLIT; s++) {
                h0 += g_ph0[s * ELEMS + idx];
                h1 += g_ph1[s * ELEMS + idx];
            }
            float nh1 = h1 / (h0 + EPSF);

            float xg = x_g[(b * NG + g) * CH + c];
            float acc = 0.f;
#pragma unroll
            for (int k = 0; k < NBAS; k++) {
                float arg = __fadd_rn(__fmul_rn(ssw[k * 3 + p], xg), ssb[k * 3 + p]);
                acc = __fadd_rn(acc, __fmul_rn(srw[k], cos_red(arg)));
            }
            float fp = SQRT_2_OVER_NBAS * acc;
            pos = nh1 + fp;

            if (jj >= HALO && jj < HALO + FG) {
                out[OFF_NH1 + idx] = nh1;
                out[OFF_FP  + idx] = fp;
                out[OFF_H0  + idx] = h0;
                g_h0s[idx] = h0;          // L2-hot mirror for k5
            }
        }
        spos[tid] = pos;
    }
    __syncthreads();

    // Phase 2: depthwise conv + per-cp partial stats
    float acc = 0.f, sq = 0.f;
    if (tid < FCONV) {
        int cp = tid >> 4;        // 0..8
        int j  = tid & 15;        // 0..15
        int c = cp / 3, p = cp % 3;
        int g = g0 + j;

        const float* w; const float* bias; int ksz, pad;
        if (p == 0)      { w = w1; bias = b1; ksz = 3; pad = 1; }
        else if (p == 1) { w = w2; bias = b2; ksz = 5; pad = 2; }
        else             { w = w3; bias = b3; ksz = 9; pad = 4; }

        acc = bias[c];
        int jj0 = j - pad + HALO;
        for (int t = 0; t < ksz; t++)
            acc = fmaf(w[c * ksz + t], spos[(jj0 + t) * 9 + cp], acc);

        g_conv[((b * NG + g) * CH + c) * NP + p] = acc;
        sq = acc * acc;
    }
    // width-16 segmented shuffle reduce
#pragma unroll
    for (int st = 8; st > 0; st >>= 1) {
        acc += __shfl_down_sync(0xffffffffu, acc, st, 16);
        sq  += __shfl_down_sync(0xffffffffu, sq,  st, 16);
    }
    if (tid < FCONV && (tid & 15) == 0) {
        int cp = tid >> 4;
        g_psum[cp * FBLOCKS + blockIdx.x] = acc;
        g_psq [cp * FBLOCKS + blockIdx.x] = sq;
    }
}

// ---------------- kernel 4b: BN finalize + g_w transpose (1 block, 9 warps) ----------------
// Warp w handles cp=w: 16 fully-unrolled strided loads per lane, width-32
// shuffle reduce, fold gamma/beta -> g_bnA/g_bnB. All threads also transpose
// g_w into g_gwt[k*64+oc] so k5's weight loads are unit-stride coalesced.
__global__ __launch_bounds__(288) void k4b_bnfin(
    const float* __restrict__ gamma, const float* __restrict__ beta,
    const float* __restrict__ gw)
{
    int tid  = threadIdx.x;
    int w    = tid >> 5;   // 0..8 == cp
    int lane = tid & 31;

    // transpose weights (1152 elems over 288 threads = 4 each)
#pragma unroll
    for (int t = tid; t < OC * 18; t += 288)
        g_gwt[(t % 18) * OC + (t / 18)] = gw[t];

    float s = 0.f, q = 0.f;
#pragma unroll
    for (int i = 0; i < FBLOCKS / 32; i++) {
        int k = lane + i * 32;
        s += g_psum[w * FBLOCKS + k];
        q += g_psq [w * FBLOCKS + k];
    }
#pragma unroll
    for (int st = 16; st > 0; st >>= 1) {
        s += __shfl_down_sync(0xffffffffu, s, st);
        q += __shfl_down_sync(0xffffffffu, q, st);
    }
    if (lane == 0) {
        const float invn = 1.0f / (float)(NB * NG);
        float m   = s * invn;
        float var = q * invn - m * m;
        float rs  = rsqrtf(var + BNEPS);
        int c = w / 3, p = w % 3;
        float ga = gamma[p * CH + c];
        float be = beta [p * CH + c];
        g_bnA[w] = rs * ga;
        g_bnB[w] = be - m * rs * ga;
    }
}

// ---------------- kernel 5: BN apply + n_f + final linear, register-resident ----------------
// grid: 256 blocks x 256 threads. Block = 32 positions x 64 oc; each thread owns
// one oc for 8 positions. Weight loads coalesced from g_gwt (unit stride);
// feat loads warp-uniform broadcasts from L2-hot scratch. NO smem, NO syncs.
__global__ __launch_bounds__(256) void k5_final(
    const float* __restrict__ gb, float* __restrict__ out)
{
    int tid = threadIdx.x;
    int oc  = tid & 63;
    int pg  = tid >> 6;          // 0..3
    int pos0 = blockIdx.x * K5_POS + pg * 8;

    // per-thread weights + bias: coalesced (lane stride = 4B)
    float wreg[18];
#pragma unroll
    for (int k = 0; k < 18; k++)
        wreg[k] = g_gwt[k * OC + oc];
    float bias = gb[oc];

    // BN constants (broadcast loads, L2-hot)
    float A[9], B[9];
#pragma unroll
    for (int k = 0; k < 9; k++) {
        A[k] = g_bnA[k];
        B[k] = g_bnB[k];
    }

#pragma unroll
    for (int i = 0; i < 8; i++) {
        int pos = pos0 + i;
        float acc = bias;
#pragma unroll
        for (int k = 0; k < 9; k++)
            acc = fmaf(g_h0s[pos * 9 + k], wreg[k], acc);
#pragma unroll
        for (int k = 0; k < 9; k++) {
            float v = fmaf(g_conv[pos * 9 + k], A[k], B[k]);
            acc = fmaf(v, wreg[9 + k], acc);
            if (oc == k)                      // unrolled: constant compare, predicated store
                out[OFF_NF + pos * 9 + k] = v;
        }
        out[pos * OC + oc] = acc;
    }
}

// ---------------- launch ----------------
extern "C" void kernel_launch(void* const* d_in, const int* in_sizes, int n_in,
                              void* d_out, int out_size)
{
    const float* x_c   = (const float*)d_in[0];
    const float* y_c   = (const float*)d_in[1];
    const float* x_g   = (const float*)d_in[2];
    const float* sigma = (const float*)d_in[3];
    const float* mu    = (const float*)d_in[4];
    const float* eps1  = (const float*)d_in[5];
    const float* b_u   = (const float*)d_in[6];
    const float* rw    = (const float*)d_in[7];
    const float* w1    = (const float*)d_in[8];
    const float* b1    = (const float*)d_in[9];
    const float* w2    = (const float*)d_in[10];
    const float* b2    = (const float*)d_in[11];
    const float* w3    = (const float*)d_in[12];
    const float* b3    = (const float*)d_in[13];
    const float* gam   = (const float*)d_in[14];
    const float* bet   = (const float*)d_in[15];
    const float* gw    = (const float*)d_in[16];
    const float* gb    = (const float*)d_in[17];
    float* out = (float*)d_out;

    k1_rbf<<<NB * GTILES * SPLIT, CH * TILE_G>>>(x_c, y_c, x_g, sigma);
    kF_fused<<<FBLOCKS, FTHREADS>>>(x_g, sigma, mu, eps1, b_u, rw,
                                    w1, b1, w2, b2, w3, b3, out);
    k4b_bnfin<<<1, 288>>>(gam, bet, gw);
    k5_final<<<K5_BLOCKS, 256>>>(gb, out);
}

// round 15
// speedup vs baseline: 1.1144x; 1.1144x over previous
#include <cuda_runtime.h>

// ---------------- problem constants ----------------
#define NB 4
#define NC 512
#define NG 2048
#define CH 3
#define NP 3
#define NBAS 10
#define OC 64
#define EPSF 1e-6f
#define BNEPS 1e-5f
#define LOG2E_F 1.4426950408889634f
#define PI2F 6.283185307179586f
#define INV2PI_F 0.15915494309189535f
#define PI2_D 6.2831853071795864769
#define SQRT_2_OVER_NBAS 0.4472135954999579f

#define SPLIT 8
#define NCHUNK (NC / SPLIT)   // 64
#define TILE_G 64
#define GTILES (NG / TILE_G)  // 32

#define ELEMS (NB * NG * CH * NP)  // 73728

// fused combine/conv kernel tiling
#define FG 16
#define FBLOCKS (NB * (NG / FG))    // 512
#define FTHREADS 224
#define HALO 4
#define FGH (FG + 2 * HALO)         // 24
#define FCONV (9 * FG)              // 144

// final kernel tiling: 8 positions x 64 oc per block, smem GEMM, 1024 blocks
#define K5_POS 8
#define K5_BLOCKS ((NB * NG) / K5_POS)  // 1024

// output offsets (flattened tuple concat: y_out, n_f, fourier, n_h1, h0_f)
#define OFF_NF  (NB * NG * OC)        // 524288
#define OFF_FP  (OFF_NF + ELEMS)      // 598016
#define OFF_NH1 (OFF_FP + ELEMS)      // 671744
#define OFF_H0  (OFF_NH1 + ELEMS)     // 745472

// ---------------- scratch (no allocs allowed) ----------------
__device__ float g_ph0[SPLIT * ELEMS];
__device__ float g_ph1[SPLIT * ELEMS];
__device__ float g_conv[ELEMS];             // conv output (pre-BN)
__device__ float g_h0s [ELEMS];             // h0 mirror (L2-hot feat source for k5)
__device__ float g_psum[9 * FBLOCKS];       // per-cp per-block partial sums
__device__ float g_psq [9 * FBLOCKS];       // per-cp per-block partial sum-squares
__device__ float g_bnA[9];                  // folded BN: v*A + B
__device__ float g_bnB[9];

__device__ __forceinline__ float ex2f(float x) {
    float y;
    asm("ex2.approx.ftz.f32 %0, %1;" : "=f"(y) : "f"(x));
    return y;
}

// ---------------- kernel 1: RBF pairwise partial sums (lean scalar, dense) ----------------
// grid: NB * GTILES * SPLIT = 1024 blocks, block: 192 threads (6 warps).
// warp w: c = w % 3 (uniform), g = gt*64 + (w/3)*32 + lane.
// Scalar math, float2 shared loads, 12 even/odd accumulators. MUFU-bound (measured 14.8us).
__global__ __launch_bounds__(CH * TILE_G) void k1_rbf(
    const float* __restrict__ x_c, const float* __restrict__ y_c,
    const float* __restrict__ x_g, const float* __restrict__ sigma)
{
    __shared__ __align__(8) float sxp[NCHUNK * CH];  // pair-interleaved x
    __shared__ __align__(8) float syp[NCHUNK * CH];

    int unit = blockIdx.x;
    int s  = unit % SPLIT;
    int gt = (unit / SPLIT) % GTILES;
    int b  = unit / (SPLIT * GTILES);

    int lane = threadIdx.x & 31;
    int w    = threadIdx.x >> 5;       // 0..5
    int c    = w % 3;                  // uniform per warp
    int g    = gt * TILE_G + (w / 3) * 32 + lane;
    int n0   = s * NCHUNK;

    const float* xb = x_c + (b * NC + n0) * CH;
    const float* yb = y_c + (b * NC + n0) * CH;
    for (int i = threadIdx.x; i < NCHUNK * CH; i += blockDim.x) {
        int n = i / CH, cc = i % CH;
        int slot = ((n >> 1) * CH + cc) * 2 + (n & 1);
        sxp[slot] = xb[i];
        syp[slot] = yb[i];
    }
    __syncthreads();

    float xg = x_g[(b * NG + g) * CH + c];

    float s0 = expf(sigma[0]) + EPSF;
    float s1 = expf(sigma[1]) + EPSF;
    float s2 = expf(sigma[2]) + EPSF;
    float k0 = -0.5f * LOG2E_F / (s0 * s0);
    float k1 = -0.5f * LOG2E_F / (s1 * s1);
    float k2 = -0.5f * LOG2E_F / (s2 * s2);

    float h00e = 0.f, h01e = 0.f, h02e = 0.f;
    float h00o = 0.f, h01o = 0.f, h02o = 0.f;
    float h10e = 0.f, h11e = 0.f, h12e = 0.f;
    float h10o = 0.f, h11o = 0.f, h12o = 0.f;

    const float2* sx2 = (const float2*)sxp;
    const float2* sy2 = (const float2*)syp;

#pragma unroll 8
    for (int n2 = 0; n2 < NCHUNK / 2; n2++) {
        float2 xv = sx2[n2 * CH + c];   // broadcast LDS.64 (warp-uniform addr)
        float2 yv = sy2[n2 * CH + c];
        float d0 = xg - xv.x;
        float d1 = xg - xv.y;
        float t0 = d0 * d0;
        float t1 = d1 * d1;
        float wv;
        wv = ex2f(t0 * k0); h00e += wv; h10e = fmaf(wv, yv.x, h10e);
        wv = ex2f(t1 * k0); h00o += wv; h10o = fmaf(wv, yv.y, h10o);
        wv = ex2f(t0 * k1); h01e += wv; h11e = fmaf(wv, yv.x, h11e);
        wv = ex2f(t1 * k1); h01o += wv; h11o = fmaf(wv, yv.y, h11o);
        wv = ex2f(t0 * k2); h02e += wv; h12e = fmaf(wv, yv.x, h12e);
        wv = ex2f(t1 * k2); h02o += wv; h12o = fmaf(wv, yv.y, h12o);
    }

    int base = ((b * NG + g) * CH + c) * NP;
    int off  = s * ELEMS + base;
    g_ph0[off + 0] = h00e + h00o;
    g_ph0[off + 1] = h01e + h01o;
    g_ph0[off + 2] = h02e + h02o;
    g_ph1[off + 0] = h10e + h10o;
    g_ph1[off + 1] = h11e + h11o;
    g_ph1[off + 2] = h12e + h12o;
}

// fp32 Cody-Waite cos for args up to ~2e5: two single-rounding FMAs remove
// n*2pi, then hardware cos on |r| <= pi+eps. abs err ~7e-7, no FP64.
__device__ __forceinline__ float cos_red(float arg) {
    const float F2PI     = (float)PI2_D;
    const float F2PI_RES = (float)(PI2_D - (double)((float)PI2_D));
    float n = rintf(arg * INV2PI_F);
    float r = fmaf(-n, F2PI, arg);
    r = fmaf(-n, F2PI_RES, r);
    return __cosf(r);
}

// ---------------- kernel F: combine + Fourier prior + depthwise conv + BN partials ----------------
// grid: 512 blocks (b x g-tile of 16), 224 threads.
__global__ __launch_bounds__(FTHREADS) void kF_fused(
    const float* __restrict__ x_g, const float* __restrict__ sigma,
    const float* __restrict__ mu,  const float* __restrict__ eps1,
    const float* __restrict__ b_u, const float* __restrict__ rw,
    const float* __restrict__ w1, const float* __restrict__ b1,
    const float* __restrict__ w2, const float* __restrict__ b2,
    const float* __restrict__ w3, const float* __restrict__ b3,
    float* __restrict__ out)
{
    __shared__ float spos[FGH * 9];       // 216
    __shared__ float ssw[NBAS * 3];
    __shared__ float ssb[NBAS * 3];
    __shared__ float srw[NBAS];

    int tid = threadIdx.x;
    int b   = blockIdx.x / (NG / FG);
    int gt  = blockIdx.x % (NG / FG);
    int g0  = gt * FG;

    if (tid < NBAS * 3) {
        int k = tid / 3, p = tid % 3;
        float wmu  = expf(mu[p]);
        float wstd = 1.0f / (expf(sigma[p]) + EPSF);
        float e = eps1[(b * NBAS + k) * NP + p];
        float u = b_u [(b * NBAS + k) * NP + p];
        ssw[tid] = __fadd_rn(wmu, __fmul_rn(wstd, e));
        ssb[tid] = __fmul_rn(PI2F, u);
    }
    if (tid < NBAS) srw[tid] = rw[tid];
    __syncthreads();

    // Phase 1: pos = n_h1 + fourier, one element per thread
    if (tid < FGH * 9) {
        int jj = tid / 9;
        int cp = tid % 9;
        int c = cp / 3, p = cp % 3;
        int g = g0 - HALO + jj;
        float pos = 0.f;
        if (g >= 0 && g < NG) {
            int idx = ((b * NG + g) * CH + c) * NP + p;
            float h0 = 0.f, h1 = 0.f;
#pragma unroll
            for (int s = 0; s < SPLIT; s++) {
                h0 += g_ph0[s * ELEMS + idx];
                h1 += g_ph1[s * ELEMS + idx];
            }
            float nh1 = h1 / (h0 + EPSF);

            float xg = x_g[(b * NG + g) * CH + c];
            float acc = 0.f;
#pragma unroll
            for (int k = 0; k < NBAS; k++) {
                float arg = __fadd_rn(__fmul_rn(ssw[k * 3 + p], xg), ssb[k * 3 + p]);
                acc = __fadd_rn(acc, __fmul_rn(srw[k], cos_red(arg)));
            }
            float fp = SQRT_2_OVER_NBAS * acc;
            pos = nh1 + fp;

            if (jj >= HALO && jj < HALO + FG) {
                out[OFF_NH1 + idx] = nh1;
                out[OFF_FP  + idx] = fp;
                out[OFF_H0  + idx] = h0;
                g_h0s[idx] = h0;          // L2-hot mirror for k5
            }
        }
        spos[tid] = pos;
    }
    __syncthreads();

    // Phase 2: depthwise conv + per-cp partial stats
    float acc = 0.f, sq = 0.f;
    if (tid < FCONV) {
        int cp = tid >> 4;        // 0..8
        int j  = tid & 15;        // 0..15
        int c = cp / 3, p = cp % 3;
        int g = g0 + j;

        const float* w; const float* bias; int ksz, pad;
        if (p == 0)      { w = w1; bias = b1; ksz = 3; pad = 1; }
        else if (p == 1) { w = w2; bias = b2; ksz = 5; pad = 2; }
        else             { w = w3; bias = b3; ksz = 9; pad = 4; }

        acc = bias[c];
        int jj0 = j - pad + HALO;
        for (int t = 0; t < ksz; t++)
            acc = fmaf(w[c * ksz + t], spos[(jj0 + t) * 9 + cp], acc);

        g_conv[((b * NG + g) * CH + c) * NP + p] = acc;
        sq = acc * acc;
    }
    // width-16 segmented shuffle reduce
#pragma unroll
    for (int st = 8; st > 0; st >>= 1) {
        acc += __shfl_down_sync(0xffffffffu, acc, st, 16);
        sq  += __shfl_down_sync(0xffffffffu, sq,  st, 16);
    }
    if (tid < FCONV && (tid & 15) == 0) {
        int cp = tid >> 4;
        g_psum[cp * FBLOCKS + blockIdx.x] = acc;
        g_psq [cp * FBLOCKS + blockIdx.x] = sq;
    }
}

// ---------------- kernel 4b: BN finalize (1 block, 9 warps) ----------------
// Warp w handles cp=w: 16 fully-unrolled strided loads per lane (high MLP),
// width-32 shuffle reduce, fold gamma/beta -> g_bnA/g_bnB.
__global__ __launch_bounds__(288) void k4b_bnfin(
    const float* __restrict__ gamma, const float* __restrict__ beta)
{
    int w    = threadIdx.x >> 5;   // 0..8 == cp
    int lane = threadIdx.x & 31;

    float s = 0.f, q = 0.f;
#pragma unroll
    for (int i = 0; i < FBLOCKS / 32; i++) {
        int k = lane + i * 32;
        s += g_psum[w * FBLOCKS + k];
        q += g_psq [w * FBLOCKS + k];
    }
#pragma unroll
    for (int st = 16; st > 0; st >>= 1) {
        s += __shfl_down_sync(0xffffffffu, s, st);
        q += __shfl_down_sync(0xffffffffu, q, st);
    }
    if (lane == 0) {
        const float invn = 1.0f / (float)(NB * NG);
        float m   = s * invn;
        float var = q * invn - m * m;
        float rs  = rsqrtf(var + BNEPS);
        int c = w / 3, p = w % 3;
        float ga = gamma[p * CH + c];
        float be = beta [p * CH + c];
        g_bnA[w] = rs * ga;
        g_bnB[w] = be - m * rs * ga;
    }
}

// ---------------- kernel 5: BN apply + n_f + final linear (18 -> 64) ----------------
// grid: 1024 blocks x 256 threads, 8 positions/block (smem GEMM, ONE sync).
// Weight stage (coalesced from gw) and feat build run concurrently pre-sync;
// post-sync each thread emits 2 outputs from smem. ~7 blocks/SM -> occ ~85%.
#define GW_STRIDE 19
__global__ __launch_bounds__(256) void k5_final(
    const float* __restrict__ gw, const float* __restrict__ gb,
    float* __restrict__ out)
{
    __shared__ float sgw[OC * GW_STRIDE];
    __shared__ float sgb[OC];
    __shared__ float sA[9], sB[9];
    __shared__ float feat[K5_POS * 18];

    int tid = threadIdx.x;
    int pos0 = blockIdx.x * K5_POS;

    // stage weights (coalesced; 4.5 loads/thread)
#pragma unroll
    for (int t = tid; t < OC * 18; t += 256)
        sgw[(t / 18) * GW_STRIDE + (t % 18)] = gw[t];
    if (tid < OC) sgb[tid] = gb[tid];
    if (tid >= 64 && tid < 73) {
        sA[tid - 64] = g_bnA[tid - 64];
        sB[tid - 64] = g_bnB[tid - 64];
    }
    // feat build: 144 elements, threads 96..239 (avoid the sA writer warp race
    // by reading g_bnA/g_bnB directly — tiny broadcast loads, L2-hot)
    if (tid >= 96 && tid < 96 + K5_POS * 18) {
        int t = tid - 96;
        int pl = t / 18, k = t % 18;
        int pos = pos0 + pl;
        float v;
        if (k < 9) {
            v = g_h0s[pos * 9 + k];
        } else {
            int cp = k - 9;
            v = fmaf(g_conv[pos * 9 + cp], g_bnA[cp], g_bnB[cp]);
            out[OFF_NF + pos * 9 + cp] = v;
        }
        feat[pl * 18 + k] = v;
    }
    __syncthreads();

    // GEMM: 2 outputs per thread
    int oc = tid & 63;
    int pg = tid >> 6;   // 0..3
#pragma unroll
    for (int i = 0; i < 2; i++) {
        int pl = pg * 2 + i;
        float acc = sgb[oc];
#pragma unroll
        for (int f = 0; f < 18; f++)
            acc = fmaf(feat[pl * 18 + f], sgw[oc * GW_STRIDE + f], acc);
        out[(pos0 + pl) * OC + oc] = acc;
    }
}

// ---------------- launch ----------------
extern "C" void kernel_launch(void* const* d_in, const int* in_sizes, int n_in,
                              void* d_out, int out_size)
{
    const float* x_c   = (const float*)d_in[0];
    const float* y_c   = (const float*)d_in[1];
    const float* x_g   = (const float*)d_in[2];
    const float* sigma = (const float*)d_in[3];
    const float* mu    = (const float*)d_in[4];
    const float* eps1  = (const float*)d_in[5];
    const float* b_u   = (const float*)d_in[6];
    const float* rw    = (const float*)d_in[7];
    const float* w1    = (const float*)d_in[8];
    const float* b1    = (const float*)d_in[9];
    const float* w2    = (const float*)d_in[10];
    const float* b2    = (const float*)d_in[11];
    const float* w3    = (const float*)d_in[12];
    const float* b3    = (const float*)d_in[13];
    const float* gam   = (const float*)d_in[14];
    const float* bet   = (const float*)d_in[15];
    const float* gw    = (const float*)d_in[16];
    const float* gb    = (const float*)d_in[17];
    float* out = (float*)d_out;

    k1_rbf<<<NB * GTILES * SPLIT, CH * TILE_G>>>(x_c, y_c, x_g, sigma);
    kF_fused<<<FBLOCKS, FTHREADS>>>(x_g, sigma, mu, eps1, b_u, rw,
                                    w1, b1, w2, b2, w3, b3, out);
    k4b_bnfin<<<1, 288>>>(gam, bet);
    k5_final<<<K5_BLOCKS, 256>>>(gw, gb, out);
}